// round 1
// baseline (speedup 1.0000x reference)
#include <cuda_runtime.h>
#include <cuda_bf16.h>
#include <math.h>

// Problem constants
#define BB 4
#define CC 256
#define HH 64
#define WW 64
#define OO 256
#define K2 9
#define KK 2304          // C * K2
#define NPIX 16384       // B*H*W
#define PTILE 16         // pixels per block in main kernel
#define OFFPIX 32        // pixels per block in offset conv

// Static device scratch (no allocations allowed)
__device__ float g_xT[BB * HH * WW * CC];          // [b][h][w][c]   16.8 MB
__device__ float g_off[BB * 18 * HH * WW];         // [b][ch][h][w]   1.2 MB
__device__ float g_woffT[18 * K2 * CC];            // [ch][tap][c]    166 KB
__device__ float g_wdefT[KK * OO];                 // [(k>>2)][o][k&3] 2.36 MB
__device__ float g_mean[OO];
__device__ float g_scale[OO];

// ---------------------------------------------------------------------------
// Kernel 1: transpose x [B][C][HW] -> xT [B][HW][C]
// ---------------------------------------------------------------------------
__global__ void k_transpose_x(const float* __restrict__ x) {
    __shared__ float tile[32][33];
    int b   = blockIdx.z;
    int hw0 = blockIdx.x * 32;
    int c0  = blockIdx.y * 32;
    tile[threadIdx.y][threadIdx.x] =
        x[(b * CC + c0 + threadIdx.y) * 4096 + hw0 + threadIdx.x];
    __syncthreads();
    g_xT[(b * 4096 + hw0 + threadIdx.y) * CC + c0 + threadIdx.x] =
        tile[threadIdx.x][threadIdx.y];
}

// ---------------------------------------------------------------------------
// Kernel 2: transpose w_off [ch][c][ky][kx] -> [ch][tap][c]
// ---------------------------------------------------------------------------
__global__ void k_transpose_woff(const float* __restrict__ w_off) {
    int idx = blockIdx.x * blockDim.x + threadIdx.x;
    if (idx >= 18 * CC * K2) return;
    int ch  = idx / (CC * K2);
    int r   = idx % (CC * K2);
    int c   = r / K2;
    int tap = r % K2;
    g_woffT[(ch * K2 + tap) * CC + c] = w_off[idx];
}

// ---------------------------------------------------------------------------
// Kernel 3: transpose w_def [o][c][k2] -> g_wdefT[(k>>2)*1024 + o*4 + (k&3)],
//           k = k2*256 + c  (matches svals layout [k2][c])
// ---------------------------------------------------------------------------
__global__ void k_transpose_wdef(const float* __restrict__ w_def) {
    int idx = blockIdx.x * blockDim.x + threadIdx.x;
    if (idx >= OO * KK) return;
    int o  = idx / KK;
    int r  = idx % KK;
    int c  = r / K2;
    int k2 = r % K2;
    int k  = k2 * CC + c;
    g_wdefT[(k >> 2) * (OO * 4) + (o << 2) + (k & 3)] = w_def[idx];
}

// ---------------------------------------------------------------------------
// Kernel 4: offset conv. Block = 256 threads (thread = input channel),
// OFFPIX pixels per block. Weights cached in smem (166 KB).
// ---------------------------------------------------------------------------
__global__ void __launch_bounds__(256, 1)
k_off_conv(const float* __restrict__ b_off) {
    extern __shared__ float smem[];                 // 18*9*256 weights + 18*8 reduce
    float* sw   = smem;
    float* sred = smem + 18 * K2 * CC;
    int t = threadIdx.x, lane = t & 31, warp = t >> 5;

    for (int i = t; i < 18 * K2 * CC; i += 256) sw[i] = g_woffT[i];
    __syncthreads();

    for (int pp = 0; pp < OFFPIX; pp++) {
        int pid = blockIdx.x * OFFPIX + pp;
        int b = pid >> 12;
        int hw = pid & 4095;
        int h = hw >> 6, w = hw & 63;

        float acc[18];
        #pragma unroll
        for (int ch = 0; ch < 18; ch++) acc[ch] = 0.f;

        #pragma unroll
        for (int tap = 0; tap < K2; tap++) {
            int ky = tap / 3, kx = tap % 3;
            int y = h - 1 + ky, x = w - 1 + kx;
            float xv = 0.f;
            if ((unsigned)y < 64u && (unsigned)x < 64u)
                xv = g_xT[(((b << 12) + (y << 6) + x) << 8) + t];
            #pragma unroll
            for (int ch = 0; ch < 18; ch++)
                acc[ch] = fmaf(xv, sw[(ch * K2 + tap) * CC + t], acc[ch]);
        }
        // warp reduce each channel
        #pragma unroll
        for (int sft = 16; sft > 0; sft >>= 1) {
            #pragma unroll
            for (int ch = 0; ch < 18; ch++)
                acc[ch] += __shfl_xor_sync(0xffffffffu, acc[ch], sft);
        }
        if (lane == 0) {
            #pragma unroll
            for (int ch = 0; ch < 18; ch++) sred[ch * 8 + warp] = acc[ch];
        }
        __syncthreads();
        if (t < 18) {
            float s = 0.f;
            #pragma unroll
            for (int i = 0; i < 8; i++) s += sred[t * 8 + i];
            g_off[((b * 18 + t) << 12) + hw] = s + b_off[t];
        }
        __syncthreads();
    }
}

// ---------------------------------------------------------------------------
// Kernel 5: main deformable conv (pre-BN), writes to out = d_out.
// Block = 256 threads (thread = output channel o), PTILE pixels/block.
// Phase 1: bilinear-gather svals[p][k2*256+c] into 144KB smem.
// Phase 2: inner product vs wdefT with LDG.128 weights + LDS.128 broadcasts.
// ---------------------------------------------------------------------------
__global__ void __launch_bounds__(256, 1)
k_main(float* __restrict__ out) {
    extern __shared__ float sv[];                   // [PTILE][KK]
    int t = threadIdx.x;
    int pid0 = blockIdx.x * PTILE;

    // ---- Phase 1: gather ----
    for (int p = 0; p < PTILE; p++) {
        int pid = pid0 + p;
        int b = pid >> 12;
        int hw = pid & 4095;
        int h = hw >> 6, w = hw & 63;
        const float* offb = g_off + ((b * 18) << 12) + hw;
        const float* xb   = g_xT + ((long)b << 20);   // b*4096*256

        #pragma unroll
        for (int k2 = 0; k2 < K2; k2++) {
            float dy = offb[(2 * k2) << 12];
            float dx = offb[(2 * k2 + 1) << 12];
            float py = dy + (float)(k2 / 3) + (float)(h - 1);
            float px = dx + (float)(k2 % 3) + (float)(w - 1);
            float y0f = floorf(py), x0f = floorf(px);
            float wy1 = py - y0f, wx1 = px - x0f;
            float wy0 = 1.f - wy1, wx0 = 1.f - wx1;
            int y0 = (int)y0f, x0 = (int)x0f;
            int y1 = y0 + 1,  x1 = x0 + 1;

            float v = 0.f;
            bool vy0 = (unsigned)y0 < 64u, vy1 = (unsigned)y1 < 64u;
            bool vx0 = (unsigned)x0 < 64u, vx1 = (unsigned)x1 < 64u;
            if (vy0 && vx0) v = fmaf(wy0 * wx0, xb[(((y0 << 6) + x0) << 8) + t], v);
            if (vy0 && vx1) v = fmaf(wy0 * wx1, xb[(((y0 << 6) + x1) << 8) + t], v);
            if (vy1 && vx0) v = fmaf(wy1 * wx0, xb[(((y1 << 6) + x0) << 8) + t], v);
            if (vy1 && vx1) v = fmaf(wy1 * wx1, xb[(((y1 << 6) + x1) << 8) + t], v);
            sv[p * KK + (k2 << 8) + t] = v;
        }
    }
    __syncthreads();

    // ---- Phase 2: GEMM ----
    float acc[PTILE];
    #pragma unroll
    for (int p = 0; p < PTILE; p++) acc[p] = 0.f;

    const float* wbase = g_wdefT + (t << 2);
    float4 wv = *(const float4*)(wbase);
    for (int kq = 0; kq < KK / 4; kq++) {
        float4 wn = make_float4(0.f, 0.f, 0.f, 0.f);
        if (kq + 1 < KK / 4) wn = *(const float4*)(wbase + (kq + 1) * (OO * 4));
        const float* svk = sv + (kq << 2);
        #pragma unroll
        for (int p = 0; p < PTILE; p++) {
            float4 s = *(const float4*)(svk + p * KK);
            acc[p] = fmaf(s.x, wv.x, acc[p]);
            acc[p] = fmaf(s.y, wv.y, acc[p]);
            acc[p] = fmaf(s.z, wv.z, acc[p]);
            acc[p] = fmaf(s.w, wv.w, acc[p]);
        }
        wv = wn;
    }

    // ---- Phase 3: store pre-BN result ----
    #pragma unroll
    for (int p = 0; p < PTILE; p++) {
        int pid = pid0 + p;
        int b = pid >> 12;
        int hw = pid & 4095;
        out[(((b << 8) + t) << 12) + hw] = acc[p];
    }
}

// ---------------------------------------------------------------------------
// Kernel 6: per-channel mean / inv-std  (block = one output channel)
// ---------------------------------------------------------------------------
__global__ void k_stats(const float* __restrict__ out,
                        const float* __restrict__ gamma) {
    int o = blockIdx.x;
    int t = threadIdx.x, lane = t & 31, warp = t >> 5;
    float s = 0.f, s2 = 0.f;
    for (int b = 0; b < BB; b++) {
        const float* p = out + (((b << 8) + o) << 12);
        for (int i = t; i < 4096; i += 256) {
            float v = p[i];
            s += v;
            s2 = fmaf(v, v, s2);
        }
    }
    #pragma unroll
    for (int sft = 16; sft > 0; sft >>= 1) {
        s  += __shfl_xor_sync(0xffffffffu, s,  sft);
        s2 += __shfl_xor_sync(0xffffffffu, s2, sft);
    }
    __shared__ float rs[8], rs2[8];
    if (lane == 0) { rs[warp] = s; rs2[warp] = s2; }
    __syncthreads();
    if (t == 0) {
        float S = 0.f, S2 = 0.f;
        #pragma unroll
        for (int i = 0; i < 8; i++) { S += rs[i]; S2 += rs2[i]; }
        float mean = S * (1.f / 16384.f);
        float var  = S2 * (1.f / 16384.f) - mean * mean;
        g_mean[o]  = mean;
        g_scale[o] = gamma[o] * rsqrtf(var + 1e-5f);
    }
}

// ---------------------------------------------------------------------------
// Kernel 7: in-place normalize + relu
// ---------------------------------------------------------------------------
__global__ void k_norm(float* __restrict__ out,
                       const float* __restrict__ beta) {
    int idx = blockIdx.x * blockDim.x + threadIdx.x;
    if (idx >= BB * OO * 4096) return;
    int o = (idx >> 12) & 255;
    float v = (out[idx] - g_mean[o]) * g_scale[o] + beta[o];
    out[idx] = fmaxf(v, 0.f);
}

// ---------------------------------------------------------------------------
extern "C" void kernel_launch(void* const* d_in, const int* in_sizes, int n_in,
                              void* d_out, int out_size) {
    const float* x     = (const float*)d_in[0];
    const float* w_off = (const float*)d_in[1];
    const float* b_off = (const float*)d_in[2];
    const float* w_def = (const float*)d_in[3];
    const float* gamma = (const float*)d_in[4];
    const float* beta  = (const float*)d_in[5];
    float* out = (float*)d_out;

    cudaFuncSetAttribute(k_off_conv, cudaFuncAttributeMaxDynamicSharedMemorySize,
                         (18 * K2 * CC + 18 * 8) * (int)sizeof(float));
    cudaFuncSetAttribute(k_main, cudaFuncAttributeMaxDynamicSharedMemorySize,
                         PTILE * KK * (int)sizeof(float));

    // transposes
    {
        dim3 grid(4096 / 32, CC / 32, BB), blk(32, 32);
        k_transpose_x<<<grid, blk>>>(x);
    }
    k_transpose_woff<<<(18 * CC * K2 + 255) / 256, 256>>>(w_off);
    k_transpose_wdef<<<(OO * KK + 255) / 256, 256>>>(w_def);

    // offset conv
    k_off_conv<<<NPIX / OFFPIX, 256,
                 (18 * K2 * CC + 18 * 8) * sizeof(float)>>>(b_off);

    // main deformable conv (pre-BN result into d_out)
    k_main<<<NPIX / PTILE, 256, PTILE * KK * sizeof(float)>>>(out);

    // batchnorm stats + normalize + relu (in-place on d_out)
    k_stats<<<OO, 256>>>(out, gamma);
    k_norm<<<(BB * OO * 4096 + 255) / 256, 256>>>(out, beta);
}

// round 3
// speedup vs baseline: 1.5709x; 1.5709x over previous
#include <cuda_runtime.h>
#include <math.h>

#define BB 4
#define CC 256
#define OO 256
#define KK 2304          // C * 9
#define NPIX 16384
#define PT 32            // pixels per block (one row segment, same h, same b)
#define ROW 260          // sv row stride in floats (1040 B, 16B-aligned)

// Static device scratch
__device__ float g_xT[BB * 4096 * CC];      // [b][hw][c]       16.8 MB
__device__ float g_woffT2[KK * 18];         // [k][ch]          166 KB
__device__ float g_wdefT[KK * OO];          // [(k>>2)][o][k&3] 2.36 MB
__device__ float g_mean[OO];
__device__ float g_scale[OO];

// ---- packed f32x2 helpers ----
#define FMA2(d,a,b,c)  asm("fma.rn.f32x2 %0,%1,%2,%3;" : "=l"(d) : "l"(a),"l"(b),"l"(c))
#define PACK2(d,lo,hi) asm("mov.b64 %0,{%1,%2};" : "=l"(d) : "f"(lo),"f"(hi))
#define UNPACK2(lo,hi,s) asm("mov.b64 {%0,%1},%2;" : "=f"(lo),"=f"(hi) : "l"(s))
#define LDSV2(a,b,addr) asm volatile("ld.shared.v2.u64 {%0,%1},[%2];" : "=l"(a),"=l"(b) : "r"(addr))

// ---------------------------------------------------------------------------
// transpose x [B][C][HW] -> xT [B][HW][C]
// ---------------------------------------------------------------------------
__global__ void k_transpose_x(const float* __restrict__ x) {
    __shared__ float tile[32][33];
    int b   = blockIdx.z;
    int hw0 = blockIdx.x * 32;
    int c0  = blockIdx.y * 32;
    tile[threadIdx.y][threadIdx.x] =
        x[(b * CC + c0 + threadIdx.y) * 4096 + hw0 + threadIdx.x];
    __syncthreads();
    g_xT[(b * 4096 + hw0 + threadIdx.y) * CC + c0 + threadIdx.x] =
        tile[threadIdx.x][threadIdx.y];
}

// ---------------------------------------------------------------------------
// transpose w_off [ch][c][tap] -> g_woffT2[(tap*256+c)*18 + ch]
// ---------------------------------------------------------------------------
__global__ void k_transpose_woff(const float* __restrict__ w_off) {
    int idx = blockIdx.x * blockDim.x + threadIdx.x;
    if (idx >= 18 * CC * 9) return;
    int ch  = idx / (CC * 9);
    int r   = idx % (CC * 9);
    int c   = r / 9;
    int tap = r % 9;
    g_woffT2[(tap * CC + c) * 18 + ch] = w_off[idx];
}

// ---------------------------------------------------------------------------
// transpose w_def [o][c][k2] -> g_wdefT[(k>>2)*1024 + o*4 + (k&3)], k=k2*256+c
// ---------------------------------------------------------------------------
__global__ void k_transpose_wdef(const float* __restrict__ w_def) {
    int idx = blockIdx.x * blockDim.x + threadIdx.x;
    if (idx >= OO * KK) return;
    int o  = idx / KK;
    int r  = idx % KK;
    int c  = r / 9;
    int k2 = r % 9;
    int k  = k2 * CC + c;
    g_wdefT[(k >> 2) * (OO * 4) + (o << 2) + (k & 3)] = w_def[idx];
}

// ---------------------------------------------------------------------------
// Fused main kernel. 256 threads, 32 pixels/block, tap-chunked.
// smem (floats): sv [32][260] (8320) | sw/spart (4608) | soff2 288*8 (2304)
//   total 15232 floats = 60928 B  -> 2 CTAs/SM
// ---------------------------------------------------------------------------
__global__ void __launch_bounds__(256, 2)
k_main(float* __restrict__ out, const float* __restrict__ b_off) {
    extern __shared__ float sm[];
    float* sv    = sm;                  // 8320 floats
    float* sw    = sm + 8320;           // 4608 floats (aliased by spart later)
    float* soff2 = sm + 12928;          // 2304 floats

    const int t    = threadIdx.x;
    const int pid0 = blockIdx.x * PT;
    const int b    = pid0 >> 12;
    const int hw0  = pid0 & 4095;
    const int h    = hw0 >> 6;          // all PT pixels share h
    const int w0   = hw0 & 63;          // 0 or 32
    const float* xb = g_xT + ((size_t)b << 20);
    const char*  xbB = (const char*)xb;

    // ================= Offset conv (fused, FFMA2, k-sliced) =================
    // thread -> (opx = t>>3, oslice = t&7); 9 accumulator pairs = (dy,dx)/tap
    unsigned long long oacc[9];
    #pragma unroll
    for (int j = 0; j < 9; j++) oacc[j] = 0ULL;
    const int opx = t >> 3, osl = t & 7;

    for (int tap = 0; tap < 9; tap++) {
        int y  = h + tap / 3 - 1;
        int kx = tap % 3 - 1;
        bool yok = (unsigned)y < 64u;
        // stage integer im2col tile: sv[px][c=t]
        #pragma unroll 8
        for (int px = 0; px < 32; px++) {
            int xx = w0 + px + kx;
            float v = 0.f;
            if (yok && (unsigned)xx < 64u) v = xb[(((y << 6) + xx) << 8) + t];
            sv[px * ROW + t] = v;
        }
        // stage offset weights for this tap: [c][18]
        const float* gsrc = g_woffT2 + tap * 4608;
        #pragma unroll
        for (int i = 0; i < 18; i++) sw[i * 256 + t] = gsrc[i * 256 + t];
        __syncthreads();
        // offset GEMM: c = 8*i + oslice (conflict-free weight reads)
        for (int i = 0; i < 32; i++) {
            int c = (i << 3) + osl;
            float sval = sv[opx * ROW + c];
            unsigned long long sp; PACK2(sp, sval, sval);
            const float* swc = sw + c * 18;
            #pragma unroll
            for (int j = 0; j < 9; j++) {
                float2 wv = *(const float2*)(swc + 2 * j);
                unsigned long long wp; PACK2(wp, wv.x, wv.y);
                FMA2(oacc[j], sp, wp, oacc[j]);
            }
        }
        __syncthreads();
    }

    // reduce k-slices -> offsets -> precompute bilinear weights & addresses
    {
        float* spart = sw;              // alias (sw dead now)
        #pragma unroll
        for (int j = 0; j < 9; j++) {
            float lo, hi; UNPACK2(lo, hi, oacc[j]);
            spart[(((opx << 3) + osl) * 9 + j) * 2 + 0] = lo;
            spart[(((opx << 3) + osl) * 9 + j) * 2 + 1] = hi;
        }
        __syncthreads();
        for (int idx = t; idx < 288; idx += 256) {
            int px = idx / 9, j = idx - px * 9;
            float dy = b_off[2 * j], dx = b_off[2 * j + 1];
            #pragma unroll
            for (int s = 0; s < 8; s++) {
                dy += spart[(((px << 3) + s) * 9 + j) * 2 + 0];
                dx += spart[(((px << 3) + s) * 9 + j) * 2 + 1];
            }
            float py  = dy + (float)(j / 3) + (float)(h - 1);
            float pxf = dx + (float)(j % 3) + (float)(w0 + px - 1);
            float y0f = floorf(py),  x0f = floorf(pxf);
            float wy1 = py - y0f,    wx1 = pxf - x0f;
            float wy0 = 1.f - wy1,   wx0 = 1.f - wx1;
            float vy0 = (y0f >= 0.f  && y0f <= 63.f) ? 1.f : 0.f;
            float vy1 = (y0f >= -1.f && y0f <= 62.f) ? 1.f : 0.f;
            float vx0 = (x0f >= 0.f  && x0f <= 63.f) ? 1.f : 0.f;
            float vx1 = (x0f >= -1.f && x0f <= 62.f) ? 1.f : 0.f;
            int y0 = min(max((int)y0f, 0), 63);
            int x0 = min(max((int)x0f, 0), 63);
            int y1 = min(max((int)y0f + 1, 0), 63);
            int x1 = min(max((int)x0f + 1, 0), 63);
            float4 wq = make_float4(wy0 * wx0 * vy0 * vx0, wy0 * wx1 * vy0 * vx1,
                                    wy1 * wx0 * vy1 * vx0, wy1 * wx1 * vy1 * vx1);
            int4 oq = make_int4((((y0 << 6) + x0) << 10), (((y0 << 6) + x1) << 10),
                                (((y1 << 6) + x0) << 10), (((y1 << 6) + x1) << 10));
            *(float4*)(soff2 + idx * 8)     = wq;
            *(int4*)  (soff2 + idx * 8 + 4) = oq;
        }
        __syncthreads();
    }

    // ================= Main GEMM, tap-chunked =================
    // thread = output channel o = t; 32 pixel accumulators (k-split f32x2)
    unsigned long long acc[32];
    #pragma unroll
    for (int p = 0; p < 32; p++) acc[p] = 0ULL;
    const float* wrow = g_wdefT + (t << 2);
    unsigned svb = (unsigned)__cvta_generic_to_shared(sv);
    const char* xbt = xbB + (t << 2);

    for (int tap = 0; tap < 9; tap++) {
        // deformed bilinear gather: sv[px][c=t]
        #pragma unroll 4
        for (int px = 0; px < 32; px++) {
            int idx = px * 9 + tap;
            float4 wq = *(const float4*)(soff2 + idx * 8);
            int4   oq = *(const int4*)  (soff2 + idx * 8 + 4);
            float v;
            v  = wq.x * *(const float*)(xbt + oq.x);
            v += wq.y * *(const float*)(xbt + oq.y);
            v += wq.z * *(const float*)(xbt + oq.z);
            v += wq.w * *(const float*)(xbt + oq.w);
            sv[px * ROW + t] = v;
        }
        __syncthreads();
        // GEMM over this tap's 64 k-quads
        const float* wt = wrow + tap * 64 * 1024;
        float4 wc = *(const float4*)(wt);
        for (int kq = 0; kq < 64; kq++) {
            float4 wn = wc;
            if (kq < 63) wn = *(const float4*)(wt + (kq + 1) * 1024);
            unsigned long long wp01, wp23;
            PACK2(wp01, wc.x, wc.y);
            PACK2(wp23, wc.z, wc.w);
            unsigned kb = svb + (unsigned)(kq << 4);
            #pragma unroll
            for (int px = 0; px < 32; px++) {
                unsigned long long sA, sB;
                LDSV2(sA, sB, kb + px * 1040);
                FMA2(acc[px], sA, wp01, acc[px]);
                FMA2(acc[px], sB, wp23, acc[px]);
            }
            wc = wn;
        }
        __syncthreads();
    }

    // store pre-BN result (each thread owns a contiguous 32-px row segment)
    float* orow = out + (((size_t)((b << 8) + t)) << 12) + hw0;
    #pragma unroll
    for (int q = 0; q < 8; q++) {
        float r[4];
        #pragma unroll
        for (int e = 0; e < 4; e++) {
            float lo, hi; UNPACK2(lo, hi, acc[q * 4 + e]);
            r[e] = lo + hi;
        }
        *(float4*)(orow + q * 4) = make_float4(r[0], r[1], r[2], r[3]);
    }
}

// ---------------------------------------------------------------------------
// per-channel mean / inv-std
// ---------------------------------------------------------------------------
__global__ void k_stats(const float* __restrict__ out,
                        const float* __restrict__ gamma) {
    int o = blockIdx.x;
    int t = threadIdx.x, lane = t & 31, warp = t >> 5;
    float s = 0.f, s2 = 0.f;
    for (int b = 0; b < BB; b++) {
        const float4* p = (const float4*)(out + (((size_t)((b << 8) + o)) << 12));
        for (int i = t; i < 1024; i += 256) {
            float4 v = p[i];
            s += v.x + v.y + v.z + v.w;
            s2 = fmaf(v.x, v.x, s2); s2 = fmaf(v.y, v.y, s2);
            s2 = fmaf(v.z, v.z, s2); s2 = fmaf(v.w, v.w, s2);
        }
    }
    #pragma unroll
    for (int sft = 16; sft > 0; sft >>= 1) {
        s  += __shfl_xor_sync(0xffffffffu, s,  sft);
        s2 += __shfl_xor_sync(0xffffffffu, s2, sft);
    }
    __shared__ float rs[8], rs2[8];
    if (lane == 0) { rs[warp] = s; rs2[warp] = s2; }
    __syncthreads();
    if (t == 0) {
        float S = 0.f, S2 = 0.f;
        #pragma unroll
        for (int i = 0; i < 8; i++) { S += rs[i]; S2 += rs2[i]; }
        float mean = S * (1.f / 16384.f);
        float var  = S2 * (1.f / 16384.f) - mean * mean;
        g_mean[o]  = mean;
        g_scale[o] = gamma[o] * rsqrtf(var + 1e-5f);
    }
}

// ---------------------------------------------------------------------------
// in-place normalize + relu (float4)
// ---------------------------------------------------------------------------
__global__ void k_norm(float* __restrict__ out,
                       const float* __restrict__ beta) {
    int i4 = blockIdx.x * blockDim.x + threadIdx.x;
    if (i4 >= BB * OO * 1024) return;
    int o = (i4 >> 10) & 255;
    float mu = g_mean[o], sc = g_scale[o], be = beta[o];
    float4 v = ((float4*)out)[i4];
    v.x = fmaxf(fmaf(v.x - mu, sc, be), 0.f);
    v.y = fmaxf(fmaf(v.y - mu, sc, be), 0.f);
    v.z = fmaxf(fmaf(v.z - mu, sc, be), 0.f);
    v.w = fmaxf(fmaf(v.w - mu, sc, be), 0.f);
    ((float4*)out)[i4] = v;
}

// ---------------------------------------------------------------------------
extern "C" void kernel_launch(void* const* d_in, const int* in_sizes, int n_in,
                              void* d_out, int out_size) {
    const float* x     = (const float*)d_in[0];
    const float* w_off = (const float*)d_in[1];
    const float* b_off = (const float*)d_in[2];
    const float* w_def = (const float*)d_in[3];
    const float* gamma = (const float*)d_in[4];
    const float* beta  = (const float*)d_in[5];
    float* out = (float*)d_out;

    cudaFuncSetAttribute(k_main, cudaFuncAttributeMaxDynamicSharedMemorySize,
                         15232 * (int)sizeof(float));

    {
        dim3 grid(4096 / 32, CC / 32, BB), blk(32, 32);
        k_transpose_x<<<grid, blk>>>(x);
    }
    k_transpose_woff<<<(18 * CC * 9 + 255) / 256, 256>>>(w_off);
    k_transpose_wdef<<<(OO * KK + 255) / 256, 256>>>(w_def);

    k_main<<<NPIX / PT, 256, 15232 * sizeof(float)>>>(out, b_off);

    k_stats<<<OO, 256>>>(out, gamma);
    k_norm<<<(BB * OO * 1024 + 255) / 256, 256>>>(out, beta);
}

// round 4
// speedup vs baseline: 2.1343x; 1.3586x over previous
#include <cuda_runtime.h>
#include <math.h>

#define BB 4
#define CC 256
#define OO 256
#define KK 2304          // C * 9
#define NPIX 16384
#define PT 32            // pixels per block (one row segment, same h, same b)
#define ROW 260          // offset-phase sv row stride (floats)

// Static device scratch
__device__ float g_xT[BB * 4096 * CC];      // [b][hw][c]   16.8 MB
__device__ float g_woffT2[KK * 18];         // [k][ch]      166 KB
__device__ float g_wdefW[KK * OO];          // [k][o]       2.36 MB
__device__ float g_mean[OO];
__device__ float g_scale[OO];

// ---- packed f32x2 helpers ----
#define FMA2(d,a,b,c)  asm("fma.rn.f32x2 %0,%1,%2,%3;" : "=l"(d) : "l"(a),"l"(b),"l"(c))
#define PACK2(d,lo,hi) asm("mov.b64 %0,{%1,%2};" : "=l"(d) : "f"(lo),"f"(hi))
#define UNPACK2(lo,hi,s) asm("mov.b64 {%0,%1},%2;" : "=f"(lo),"=f"(hi) : "l"(s))
#define LDS128F(s,addr) asm volatile("ld.shared.v4.f32 {%0,%1,%2,%3},[%4];" \
    : "=f"(s.x),"=f"(s.y),"=f"(s.z),"=f"(s.w) : "r"(addr))

// ---------------------------------------------------------------------------
// transpose x [B][C][HW] -> xT [B][HW][C]
// ---------------------------------------------------------------------------
__global__ void k_transpose_x(const float* __restrict__ x) {
    __shared__ float tile[32][33];
    int b   = blockIdx.z;
    int hw0 = blockIdx.x * 32;
    int c0  = blockIdx.y * 32;
    tile[threadIdx.y][threadIdx.x] =
        x[(b * CC + c0 + threadIdx.y) * 4096 + hw0 + threadIdx.x];
    __syncthreads();
    g_xT[(b * 4096 + hw0 + threadIdx.y) * CC + c0 + threadIdx.x] =
        tile[threadIdx.x][threadIdx.y];
}

// ---------------------------------------------------------------------------
// transpose w_off [ch][c][tap] -> g_woffT2[(tap*256+c)*18 + ch]
// ---------------------------------------------------------------------------
__global__ void k_transpose_woff(const float* __restrict__ w_off) {
    int idx = blockIdx.x * blockDim.x + threadIdx.x;
    if (idx >= 18 * CC * 9) return;
    int ch  = idx / (CC * 9);
    int r   = idx % (CC * 9);
    int c   = r / 9;
    int tap = r % 9;
    g_woffT2[(tap * CC + c) * 18 + ch] = w_off[idx];
}

// ---------------------------------------------------------------------------
// transpose w_def [o][c][k2] -> g_wdefW[(k2*256+c)*256 + o]
// ---------------------------------------------------------------------------
__global__ void k_transpose_wdef(const float* __restrict__ w_def) {
    int idx = blockIdx.x * blockDim.x + threadIdx.x;
    if (idx >= OO * KK) return;
    int o = idx & 255;
    int k = idx >> 8;            // k = k2*256 + c
    int c = k & 255;
    int k2 = k >> 8;
    g_wdefW[idx] = w_def[o * KK + c * 9 + k2];
}

// ---------------------------------------------------------------------------
// Fused main kernel. 256 threads, 32 pixels/block, tap-chunked SGEMM mapping.
// smem (floats): sv region max(8320 offset-layout, 8192 gemm-layout) = 8320
//                | sw/spart 4608 | soff2 2304  -> 15232 floats = 60928 B
// ---------------------------------------------------------------------------
__global__ void __launch_bounds__(256, 2)
k_main(float* __restrict__ out, const float* __restrict__ b_off) {
    extern __shared__ float sm[];
    float* sv    = sm;                  // 8320 floats (both layouts)
    float* sw    = sm + 8320;           // 4608 floats (aliased by spart)
    float* soff2 = sm + 12928;          // 2304 floats

    const int t    = threadIdx.x;
    const int pid0 = blockIdx.x * PT;
    const int b    = pid0 >> 12;
    const int hw0  = pid0 & 4095;
    const int h    = hw0 >> 6;
    const int w0   = hw0 & 63;
    const float* xb  = g_xT + ((size_t)b << 20);
    const char*  xbt = (const char*)xb + (t << 2);

    // ================= Offset conv (validated R3 code) =================
    unsigned long long oacc[9];
    #pragma unroll
    for (int j = 0; j < 9; j++) oacc[j] = 0ULL;
    const int opx = t >> 3, osl = t & 7;

    for (int tap = 0; tap < 9; tap++) {
        int y  = h + tap / 3 - 1;
        int kx = tap % 3 - 1;
        bool yok = (unsigned)y < 64u;
        #pragma unroll 8
        for (int px = 0; px < 32; px++) {
            int xx = w0 + px + kx;
            float v = 0.f;
            if (yok && (unsigned)xx < 64u) v = xb[(((y << 6) + xx) << 8) + t];
            sv[px * ROW + t] = v;
        }
        const float* gsrc = g_woffT2 + tap * 4608;
        #pragma unroll
        for (int i = 0; i < 18; i++) sw[i * 256 + t] = gsrc[i * 256 + t];
        __syncthreads();
        for (int i = 0; i < 32; i++) {
            int c = (i << 3) + osl;
            float sval = sv[opx * ROW + c];
            unsigned long long sp; PACK2(sp, sval, sval);
            const float* swc = sw + c * 18;
            #pragma unroll
            for (int j = 0; j < 9; j++) {
                float2 wv = *(const float2*)(swc + 2 * j);
                unsigned long long wp; PACK2(wp, wv.x, wv.y);
                FMA2(oacc[j], sp, wp, oacc[j]);
            }
        }
        __syncthreads();
    }

    {   // reduce k-slices -> offsets -> gather descriptors
        float* spart = sw;
        #pragma unroll
        for (int j = 0; j < 9; j++) {
            float lo, hi; UNPACK2(lo, hi, oacc[j]);
            spart[(((opx << 3) + osl) * 9 + j) * 2 + 0] = lo;
            spart[(((opx << 3) + osl) * 9 + j) * 2 + 1] = hi;
        }
        __syncthreads();
        for (int idx = t; idx < 288; idx += 256) {
            int px = idx / 9, j = idx - px * 9;
            float dy = b_off[2 * j], dx = b_off[2 * j + 1];
            #pragma unroll
            for (int s = 0; s < 8; s++) {
                dy += spart[(((px << 3) + s) * 9 + j) * 2 + 0];
                dx += spart[(((px << 3) + s) * 9 + j) * 2 + 1];
            }
            float py  = dy + (float)(j / 3) + (float)(h - 1);
            float pxf = dx + (float)(j % 3) + (float)(w0 + px - 1);
            float y0f = floorf(py),  x0f = floorf(pxf);
            float wy1 = py - y0f,    wx1 = pxf - x0f;
            float wy0 = 1.f - wy1,   wx0 = 1.f - wx1;
            float vy0 = (y0f >= 0.f  && y0f <= 63.f) ? 1.f : 0.f;
            float vy1 = (y0f >= -1.f && y0f <= 62.f) ? 1.f : 0.f;
            float vx0 = (x0f >= 0.f  && x0f <= 63.f) ? 1.f : 0.f;
            float vx1 = (x0f >= -1.f && x0f <= 62.f) ? 1.f : 0.f;
            int y0 = min(max((int)y0f, 0), 63);
            int x0 = min(max((int)x0f, 0), 63);
            int y1 = min(max((int)y0f + 1, 0), 63);
            int x1 = min(max((int)x0f + 1, 0), 63);
            float4 wq = make_float4(wy0 * wx0 * vy0 * vx0, wy0 * wx1 * vy0 * vx1,
                                    wy1 * wx0 * vy1 * vx0, wy1 * wx1 * vy1 * vx1);
            int4 oq = make_int4((((y0 << 6) + x0) << 10), (((y0 << 6) + x1) << 10),
                                (((y1 << 6) + x0) << 10), (((y1 << 6) + x1) << 10));
            *(float4*)(soff2 + idx * 8)     = wq;
            *(int4*)  (soff2 + idx * 8 + 4) = oq;
        }
        __syncthreads();
    }

    // ================= Main GEMM: SGEMM lane mapping =================
    // lane: og = (t&31)>>3 (8-o tile), pxq = t&7 (4-px tile); warp = 32 o.
    const int pxq = t & 7;
    const int og  = (t & 31) >> 3;
    const int wo  = ((t >> 5) << 5) + (og << 3);    // base output channel

    unsigned long long acc[16];                     // [e][op] : 4 px x 4 o-pairs
    #pragma unroll
    for (int i = 0; i < 16; i++) acc[i] = 0ULL;

    unsigned svb = (unsigned)__cvta_generic_to_shared(sv);
    char* svc = (char*)sv;

    for (int tap = 0; tap < 9; tap++) {
        // ---- gather into sv[c=t][px] with tile-of-4 xor swizzle ----
        #pragma unroll 2
        for (int q = 0; q < 8; q++) {
            float v[4];
            #pragma unroll
            for (int e = 0; e < 4; e++) {
                int idx = (q * 4 + e) * 9 + tap;
                float4 wq = *(const float4*)(soff2 + idx * 8);
                int4   oq = *(const int4*)  (soff2 + idx * 8 + 4);
                float vv;
                vv  = wq.x * *(const float*)(xbt + oq.x);
                vv += wq.y * *(const float*)(xbt + oq.y);
                vv += wq.z * *(const float*)(xbt + oq.z);
                vv += wq.w * *(const float*)(xbt + oq.w);
                v[e] = vv;
            }
            *(float4*)(svc + (t << 7) + (((q ^ t) & 7) << 4)) =
                make_float4(v[0], v[1], v[2], v[3]);
        }
        __syncthreads();

        // ---- GEMM over this tap's 256 k ----
        const float* wtap = g_wdefW + (size_t)(tap * 256) * 256 + wo;
        #pragma unroll 1
        for (int c8 = 0; c8 < 256; c8 += 8) {
            #pragma unroll
            for (int j = 0; j < 8; j++) {
                int c = c8 + j;
                float4 s;
                unsigned a = svb + (unsigned)(c << 7) + (unsigned)((((pxq ^ j) & 7)) << 4);
                LDS128F(s, a);
                const unsigned long long* wp =
                    (const unsigned long long*)(wtap + c * 256);
                unsigned long long w0v = wp[0], w1v = wp[1],
                                   w2v = wp[2], w3v = wp[3];
                unsigned long long sd0, sd1, sd2, sd3;
                PACK2(sd0, s.x, s.x); PACK2(sd1, s.y, s.y);
                PACK2(sd2, s.z, s.z); PACK2(sd3, s.w, s.w);
                FMA2(acc[0],  sd0, w0v, acc[0]);  FMA2(acc[1],  sd0, w1v, acc[1]);
                FMA2(acc[2],  sd0, w2v, acc[2]);  FMA2(acc[3],  sd0, w3v, acc[3]);
                FMA2(acc[4],  sd1, w0v, acc[4]);  FMA2(acc[5],  sd1, w1v, acc[5]);
                FMA2(acc[6],  sd1, w2v, acc[6]);  FMA2(acc[7],  sd1, w3v, acc[7]);
                FMA2(acc[8],  sd2, w0v, acc[8]);  FMA2(acc[9],  sd2, w1v, acc[9]);
                FMA2(acc[10], sd2, w2v, acc[10]); FMA2(acc[11], sd2, w3v, acc[11]);
                FMA2(acc[12], sd3, w0v, acc[12]); FMA2(acc[13], sd3, w1v, acc[13]);
                FMA2(acc[14], sd3, w2v, acc[14]); FMA2(acc[15], sd3, w3v, acc[15]);
            }
        }
        __syncthreads();
    }

    // ---- store pre-BN result: 4 px x 8 o per thread ----
    #pragma unroll
    for (int op = 0; op < 4; op++) {
        float l0, h0, l1, h1, l2, h2, l3, h3;
        UNPACK2(l0, h0, acc[0 * 4 + op]);
        UNPACK2(l1, h1, acc[1 * 4 + op]);
        UNPACK2(l2, h2, acc[2 * 4 + op]);
        UNPACK2(l3, h3, acc[3 * 4 + op]);
        int oe = wo + 2 * op;
        float* pe = out + (((size_t)((b << 8) + oe))     << 12) + hw0 + (pxq << 2);
        float* po = out + (((size_t)((b << 8) + oe + 1)) << 12) + hw0 + (pxq << 2);
        *(float4*)pe = make_float4(l0, l1, l2, l3);
        *(float4*)po = make_float4(h0, h1, h2, h3);
    }
}

// ---------------------------------------------------------------------------
// per-channel mean / inv-std
// ---------------------------------------------------------------------------
__global__ void k_stats(const float* __restrict__ out,
                        const float* __restrict__ gamma) {
    int o = blockIdx.x;
    int t = threadIdx.x, lane = t & 31, warp = t >> 5;
    float s = 0.f, s2 = 0.f;
    for (int b = 0; b < BB; b++) {
        const float4* p = (const float4*)(out + (((size_t)((b << 8) + o)) << 12));
        for (int i = t; i < 1024; i += 256) {
            float4 v = p[i];
            s += v.x + v.y + v.z + v.w;
            s2 = fmaf(v.x, v.x, s2); s2 = fmaf(v.y, v.y, s2);
            s2 = fmaf(v.z, v.z, s2); s2 = fmaf(v.w, v.w, s2);
        }
    }
    #pragma unroll
    for (int sft = 16; sft > 0; sft >>= 1) {
        s  += __shfl_xor_sync(0xffffffffu, s,  sft);
        s2 += __shfl_xor_sync(0xffffffffu, s2, sft);
    }
    __shared__ float rs[8], rs2[8];
    if (lane == 0) { rs[warp] = s; rs2[warp] = s2; }
    __syncthreads();
    if (t == 0) {
        float S = 0.f, S2 = 0.f;
        #pragma unroll
        for (int i = 0; i < 8; i++) { S += rs[i]; S2 += rs2[i]; }
        float mean = S * (1.f / 16384.f);
        float var  = S2 * (1.f / 16384.f) - mean * mean;
        g_mean[o]  = mean;
        g_scale[o] = gamma[o] * rsqrtf(var + 1e-5f);
    }
}

// ---------------------------------------------------------------------------
// in-place normalize + relu (float4)
// ---------------------------------------------------------------------------
__global__ void k_norm(float* __restrict__ out,
                       const float* __restrict__ beta) {
    int i4 = blockIdx.x * blockDim.x + threadIdx.x;
    if (i4 >= BB * OO * 1024) return;
    int o = (i4 >> 10) & 255;
    float mu = g_mean[o], sc = g_scale[o], be = beta[o];
    float4 v = ((float4*)out)[i4];
    v.x = fmaxf(fmaf(v.x - mu, sc, be), 0.f);
    v.y = fmaxf(fmaf(v.y - mu, sc, be), 0.f);
    v.z = fmaxf(fmaf(v.z - mu, sc, be), 0.f);
    v.w = fmaxf(fmaf(v.w - mu, sc, be), 0.f);
    ((float4*)out)[i4] = v;
}

// ---------------------------------------------------------------------------
extern "C" void kernel_launch(void* const* d_in, const int* in_sizes, int n_in,
                              void* d_out, int out_size) {
    const float* x     = (const float*)d_in[0];
    const float* w_off = (const float*)d_in[1];
    const float* b_off = (const float*)d_in[2];
    const float* w_def = (const float*)d_in[3];
    const float* gamma = (const float*)d_in[4];
    const float* beta  = (const float*)d_in[5];
    float* out = (float*)d_out;

    cudaFuncSetAttribute(k_main, cudaFuncAttributeMaxDynamicSharedMemorySize,
                         15232 * (int)sizeof(float));

    {
        dim3 grid(4096 / 32, CC / 32, BB), blk(32, 32);
        k_transpose_x<<<grid, blk>>>(x);
    }
    k_transpose_woff<<<(18 * CC * 9 + 255) / 256, 256>>>(w_off);
    k_transpose_wdef<<<(OO * KK + 255) / 256, 256>>>(w_def);

    k_main<<<NPIX / PT, 256, 15232 * sizeof(float)>>>(out, b_off);

    k_stats<<<OO, 256>>>(out, gamma);
    k_norm<<<(BB * OO * 1024 + 255) / 256, 256>>>(out, beta);
}